// round 8
// baseline (speedup 1.0000x reference)
#include <cuda_runtime.h>
#include <cuda_bf16.h>
#include <cstdint>

// ---------------------------------------------------------------------------
// KMeans assignment via warp-level bf16 HMMA (mma.sync, base sm_103 features).
//   x: (32768,512) f32, centroids: (2048,512) f32
//   labels = argmin_k ( c_sq[k] - 2*(x+eps).c_k ); assigned = centroids[labels]
// bf16x3 limbs: dot ~= xh.ch + xh.cl + xl.ch (fp32 acc), err ~1e-3 abs.
// Rows with (best2-best1) < MARGIN get an exact fp32 recompute in finalize.
// ---------------------------------------------------------------------------

#define EPSF   1e-6f
#define DIMS   512
#define MARGIN 0.02f
#define MAX_B  32768
#define MAX_K  2048

#define TM 128          // rows per CTA
#define TN 128          // centroids per n-tile
#define NTHREADS 256    // 8 warps: 4 (m) x 2 (n); warp tile 32x64

__device__ __nv_bfloat16 g_xpk[(size_t)MAX_B * 1024];   // [row][ hi512 | lo512 ]
__device__ __nv_bfloat16 g_cpk[(size_t)MAX_K * 1024];
__device__ float g_csq[MAX_K];
__device__ int   g_labels[MAX_B];
__device__ float g_gap[MAX_B];

// ------------------------------ helpers -------------------------------------
__device__ __forceinline__ uint32_t smem_u32(const void* p) {
    uint32_t a;
    asm("{ .reg .u64 t; cvta.to.shared.u64 t, %1; cvt.u32.u64 %0, t; }"
        : "=r"(a) : "l"(p));
    return a;
}
#define SWZ128(o) ((o) ^ (((o) >> 3) & 0x70))

__device__ __forceinline__ void cp_async16(uint32_t s, const void* g) {
    asm volatile("cp.async.cg.shared.global [%0], [%1], 16;"
                 :: "r"(s), "l"(g) : "memory");
}
#define CP_COMMIT() asm volatile("cp.async.commit_group;" ::: "memory")
#define CP_WAIT1()  asm volatile("cp.async.wait_group 1;" ::: "memory")

__device__ __forceinline__ void ldsm_x4(uint32_t a, uint32_t& r0, uint32_t& r1,
                                        uint32_t& r2, uint32_t& r3) {
    asm volatile("ldmatrix.sync.aligned.m8n8.x4.shared.b16 {%0,%1,%2,%3}, [%4];"
                 : "=r"(r0), "=r"(r1), "=r"(r2), "=r"(r3) : "r"(a));
}
__device__ __forceinline__ void ldsm_x2(uint32_t a, uint32_t& r0, uint32_t& r1) {
    asm volatile("ldmatrix.sync.aligned.m8n8.x2.shared.b16 {%0,%1}, [%2];"
                 : "=r"(r0), "=r"(r1) : "r"(a));
}
__device__ __forceinline__ void mma16816(float* d, const uint32_t* a,
                                         const uint32_t* b) {
    asm volatile(
        "mma.sync.aligned.m16n8k16.row.col.f32.bf16.bf16.f32 "
        "{%0,%1,%2,%3}, {%4,%5,%6,%7}, {%8,%9}, {%0,%1,%2,%3};"
        : "+f"(d[0]), "+f"(d[1]), "+f"(d[2]), "+f"(d[3])
        : "r"(a[0]), "r"(a[1]), "r"(a[2]), "r"(a[3]), "r"(b[0]), "r"(b[1]));
}
__device__ __forceinline__ uint32_t pack_bf(__nv_bfloat16 a, __nv_bfloat16 b) {
    __nv_bfloat162 t; t.x = a; t.y = b;
    return *reinterpret_cast<uint32_t*>(&t);
}
__device__ __forceinline__ unsigned sortable_f32(float f) {
    unsigned u = __float_as_uint(f);
    return (u & 0x80000000u) ? ~u : (u | 0x80000000u);
}
__device__ __forceinline__ float unsortable_f32(unsigned u) {
    return (u & 0x80000000u) ? __uint_as_float(u ^ 0x80000000u)
                             : __uint_as_float(~u);
}

// ---- prep: split fp32 rows into bf16 hi/lo limbs: [hi 512 | lo 512] --------
// warp per row: lane-coalesced loads and stores.
__global__ void prep_kernel(const float* __restrict__ src, int is_x, int nrows) {
    int warp = (blockIdx.x * 256 + threadIdx.x) >> 5;
    int lane = threadIdx.x & 31;
    if (warp >= nrows) return;
    const int row = warp;
    const float eps = is_x ? EPSF : 0.f;
    const float4* s4 = reinterpret_cast<const float4*>(src + (size_t)row * DIMS);
    uint2* dst = reinterpret_cast<uint2*>(is_x ? g_xpk : g_cpk);  // row stride 256
#pragma unroll
    for (int q = 0; q < 4; ++q) {
        float4 f = s4[q * 32 + lane];
        float e0 = f.x + eps, e1 = f.y + eps, e2 = f.z + eps, e3 = f.w + eps;
        __nv_bfloat16 h0 = __float2bfloat16(e0), h1 = __float2bfloat16(e1);
        __nv_bfloat16 h2 = __float2bfloat16(e2), h3 = __float2bfloat16(e3);
        __nv_bfloat16 l0 = __float2bfloat16(e0 - __bfloat162float(h0));
        __nv_bfloat16 l1 = __float2bfloat16(e1 - __bfloat162float(h1));
        __nv_bfloat16 l2 = __float2bfloat16(e2 - __bfloat162float(h2));
        __nv_bfloat16 l3 = __float2bfloat16(e3 - __bfloat162float(h3));
        dst[(size_t)row * 256 + q * 32 + lane] =
            make_uint2(pack_bf(h0, h1), pack_bf(h2, h3));
        dst[(size_t)row * 256 + 128 + q * 32 + lane] =
            make_uint2(pack_bf(l0, l1), pack_bf(l2, l3));
    }
}

// ---- centroid squared norms (warp per row) ----------------------------------
__global__ void csq_kernel(const float* __restrict__ cent, int K) {
    int gt = blockIdx.x * 256 + threadIdx.x;
    int w = gt >> 5, lane = gt & 31;
    if (w >= K) return;
    const float4* row = reinterpret_cast<const float4*>(cent + (size_t)w * DIMS);
    float s = 0.f;
#pragma unroll
    for (int i = 0; i < 4; ++i) {
        float4 v = row[lane + 32 * i];
        s += v.x * v.x + v.y * v.y + v.z * v.z + v.w * v.w;
    }
#pragma unroll
    for (int o = 16; o; o >>= 1) s += __shfl_xor_sync(0xffffffffu, s, o);
    if (!lane) g_csq[w] = s;
}

// ---- main HMMA kernel --------------------------------------------------------
// smem: best1[128] u64, best2[128] u32, then 3 stages of (A 16KB + B 16KB).
#define STAGE_BYTES (TM * 128 + TN * 128)  // 32768
#define SM_STAGE0   2048
#define SM_BYTES    (SM_STAGE0 + 3 * STAGE_BYTES)  // 100352

__global__ __launch_bounds__(NTHREADS, 2)
void assign_mma_kernel(int K) {
    extern __shared__ char smem[];
    unsigned long long* best1 = reinterpret_cast<unsigned long long*>(smem);
    unsigned* best2 = reinterpret_cast<unsigned*>(smem + TM * 8);
    const uint32_t sb = smem_u32(smem);

    const int tid = threadIdx.x;
    const int lane = tid & 31;
    const int wid = tid >> 5;
    const int warp_m = wid & 3;   // 4 warps along M (32 rows each)
    const int warp_n = wid >> 2;  // 2 warps along N (64 cols each)
    const int m0 = blockIdx.x * TM;

    if (tid < TM) { best1[tid] = ~0ull; best2[tid] = 0xFFFFFFFFu; }

    const int NT = K / TN;          // 16 n-tiles
    const int T = NT * 24;          // 24 k-iters per n-tile (3 products x 8)

    auto load_stage = [&](int j) {
        const int nt = j / 24, kc = j % 24;
        const int p = kc >> 3, c = kc & 7;
        const int ka = (p < 2 ? 0 : 512) + c * 64;
        const int kb = (p == 1 ? 512 : 0) + c * 64;
        const int n0 = nt * TN;
        const uint32_t abase = sb + SM_STAGE0 + (j % 3) * STAGE_BYTES;
        const uint32_t bbase = abase + TM * 128;
#pragma unroll
        for (int i = 0; i < 4; ++i) {  // A: 1024 16B chunks / 256 thr
            int idx = i * NTHREADS + tid;
            int r = idx >> 3, q = idx & 7;
            cp_async16(abase + SWZ128(r * 128 + q * 16),
                       g_xpk + (size_t)(m0 + r) * 1024 + ka + q * 8);
        }
#pragma unroll
        for (int i = 0; i < 4; ++i) {  // B: 1024 chunks / 256 thr
            int idx = i * NTHREADS + tid;
            int r = idx >> 3, q = idx & 7;
            cp_async16(bbase + SWZ128(r * 128 + q * 16),
                       g_cpk + (size_t)(n0 + r) * 1024 + kb + q * 8);
        }
    };

    float acc[2][8][4];
#pragma unroll
    for (int fm = 0; fm < 2; ++fm)
#pragma unroll
        for (int fn = 0; fn < 8; ++fn)
#pragma unroll
            for (int q = 0; q < 4; ++q) acc[fm][fn][q] = 0.f;

    float rb1[4], rb2[4];
    int ri[4];
#pragma unroll
    for (int s = 0; s < 4; ++s) {
        rb1[s] = __int_as_float(0x7f800000);
        rb2[s] = rb1[s];
        ri[s] = 0;
    }

    load_stage(0); CP_COMMIT();
    load_stage(1); CP_COMMIT();

    for (int j = 0; j < T; ++j) {
        CP_WAIT1();
        __syncthreads();
        const uint32_t abase = sb + SM_STAGE0 + (j % 3) * STAGE_BYTES;
        const uint32_t bbase = abase + TM * 128;

#pragma unroll
        for (int ks = 0; ks < 4; ++ks) {
            uint32_t a[2][4], b[8][2];
#pragma unroll
            for (int fm = 0; fm < 2; ++fm) {
                int r = warp_m * 32 + fm * 16 + (lane & 15);
                uint32_t addr = abase +
                    SWZ128((uint32_t)(r * 128 + ks * 32 + ((lane >> 4) & 1) * 16));
                ldsm_x4(addr, a[fm][0], a[fm][1], a[fm][2], a[fm][3]);
            }
#pragma unroll
            for (int fn = 0; fn < 8; ++fn) {
                int r = warp_n * 64 + fn * 8 + (lane & 7);
                uint32_t addr = bbase +
                    SWZ128((uint32_t)(r * 128 + ks * 32 + ((lane >> 3) & 1) * 16));
                ldsm_x2(addr, b[fn][0], b[fn][1]);
            }
#pragma unroll
            for (int fm = 0; fm < 2; ++fm)
#pragma unroll
                for (int fn = 0; fn < 8; ++fn)
                    mma16816(acc[fm][fn], a[fm], b[fn]);
        }

        if (j + 2 < T) load_stage(j + 2);
        CP_COMMIT();

        if ((j % 24) == 23) {
            const int n0 = (j / 24) * TN;
#pragma unroll
            for (int fn = 0; fn < 8; ++fn) {
                int c0 = n0 + warp_n * 64 + fn * 8 + (lane & 3) * 2;
                float q0 = g_csq[c0], q1 = g_csq[c0 + 1];
#pragma unroll
                for (int fm = 0; fm < 2; ++fm) {
                    float s00 = fmaf(-2.f, acc[fm][fn][0], q0);
                    float s01 = fmaf(-2.f, acc[fm][fn][1], q1);
                    float s10 = fmaf(-2.f, acc[fm][fn][2], q0);
                    float s11 = fmaf(-2.f, acc[fm][fn][3], q1);
                    int s0 = fm * 2, s1 = fm * 2 + 1;
                    if (s00 < rb1[s0]) { rb2[s0] = rb1[s0]; rb1[s0] = s00; ri[s0] = c0; }
                    else if (s00 < rb2[s0]) rb2[s0] = s00;
                    if (s01 < rb1[s0]) { rb2[s0] = rb1[s0]; rb1[s0] = s01; ri[s0] = c0 + 1; }
                    else if (s01 < rb2[s0]) rb2[s0] = s01;
                    if (s10 < rb1[s1]) { rb2[s1] = rb1[s1]; rb1[s1] = s10; ri[s1] = c0; }
                    else if (s10 < rb2[s1]) rb2[s1] = s10;
                    if (s11 < rb1[s1]) { rb2[s1] = rb1[s1]; rb1[s1] = s11; ri[s1] = c0 + 1; }
                    else if (s11 < rb2[s1]) rb2[s1] = s11;
                    acc[fm][fn][0] = 0.f; acc[fm][fn][1] = 0.f;
                    acc[fm][fn][2] = 0.f; acc[fm][fn][3] = 0.f;
                }
            }
        }
    }

    // ---- final reduction: lanes sharing a row (same lane>>2) merge ----------
#pragma unroll
    for (int s = 0; s < 4; ++s) {
#pragma unroll
        for (int d = 1; d <= 2; d <<= 1) {
            float ob1 = __shfl_xor_sync(0xffffffffu, rb1[s], d);
            float ob2 = __shfl_xor_sync(0xffffffffu, rb2[s], d);
            int oi = __shfl_xor_sync(0xffffffffu, ri[s], d);
            if (ob1 < rb1[s] || (ob1 == rb1[s] && oi < ri[s])) {
                rb2[s] = fminf(rb1[s], ob2);
                rb1[s] = ob1; ri[s] = oi;
            } else {
                rb2[s] = fminf(rb2[s], ob1);
            }
        }
    }
    if ((lane & 3) == 0) {
#pragma unroll
        for (int s = 0; s < 4; ++s) {
            int row = warp_m * 32 + (s >> 1) * 16 + (lane >> 2) + (s & 1) * 8;
            unsigned long long key =
                ((unsigned long long)sortable_f32(rb1[s]) << 32) | (unsigned)ri[s];
            atomicMin(&best1[row], key);
        }
    }
    __syncthreads();
    if ((lane & 3) == 0) {
#pragma unroll
        for (int s = 0; s < 4; ++s) {
            int row = warp_m * 32 + (s >> 1) * 16 + (lane >> 2) + (s & 1) * 8;
            unsigned long long k1 = best1[row];
            float contrib = ((int)(k1 & 0xFFFFFFFFull) == ri[s]) ? rb2[s] : rb1[s];
            atomicMin(&best2[row], sortable_f32(contrib));
        }
    }
    __syncthreads();
    if (tid < TM) {
        unsigned long long k1 = best1[tid];
        g_labels[m0 + tid] = (int)(k1 & 0xFFFFFFFFull);
        g_gap[m0 + tid] =
            unsortable_f32(best2[tid]) - unsortable_f32((unsigned)(k1 >> 32));
    }
}

// ---- finalize: exact recompute for ambiguous rows + labels + gather ---------
__global__ __launch_bounds__(128)
void finalize_kernel(const float* __restrict__ x, const float* __restrict__ cent,
                     float* __restrict__ out_labels,
                     float* __restrict__ out_assigned, int K) {
    const int row = blockIdx.x;
    const int tid = threadIdx.x;
    __shared__ float xr[DIMS];
    __shared__ unsigned long long best;
    __shared__ int s_label;

    if (g_gap[row] < MARGIN) {
        if (tid == 0) best = ~0ull;
        reinterpret_cast<float4*>(xr)[tid] =
            reinterpret_cast<const float4*>(x + (size_t)row * DIMS)[tid];
        __syncthreads();
        if (tid < DIMS) {  // add eps (128 thr x 4)
            float4* p = reinterpret_cast<float4*>(xr) + tid;
            float4 v = *p;
            v.x += EPSF; v.y += EPSF; v.z += EPSF; v.w += EPSF;
            *p = v;
        }
        __syncthreads();
        const float4* xr4 = reinterpret_cast<const float4*>(xr);
        unsigned long long lbest = ~0ull;
        for (int c = tid; c < K; c += 128) {
            const float4* cr = reinterpret_cast<const float4*>(cent + (size_t)c * DIMS);
            float s = 0.f;
#pragma unroll 8
            for (int i = 0; i < DIMS / 4; ++i) {
                float4 v = cr[i], u = xr4[i];
                s += u.x * v.x + u.y * v.y + u.z * v.z + u.w * v.w;
            }
            float score = g_csq[c] - 2.f * s;
            unsigned long long key =
                ((unsigned long long)sortable_f32(score) << 32) | (unsigned)c;
            if (key < lbest) lbest = key;
        }
        atomicMin(&best, lbest);
        __syncthreads();
        if (tid == 0) s_label = (int)(best & 0xFFFFFFFFull);
    } else {
        if (tid == 0) s_label = g_labels[row];
    }
    __syncthreads();
    const int lab = s_label;
    if (out_labels && tid == 0) out_labels[row] = (float)lab;
    if (out_assigned) {
        reinterpret_cast<float4*>(out_assigned + (size_t)row * DIMS)[tid] =
            reinterpret_cast<const float4*>(cent + (size_t)lab * DIMS)[tid];
    }
}

// ---------------------------------------------------------------------------
extern "C" void kernel_launch(void* const* d_in, const int* in_sizes, int n_in,
                              void* d_out, int out_size) {
    const float* x = (const float*)d_in[0];
    const float* cent = (const float*)d_in[1];
    const int B = in_sizes[0] / DIMS;  // 32768
    const int K = in_sizes[1] / DIMS;  // 2048

    float* out = (float*)d_out;
    float* out_labels = nullptr;
    float* out_assigned = nullptr;
    if (out_size == B * (DIMS + 1)) { out_labels = out; out_assigned = out + B; }
    else if (out_size == B * DIMS)  { out_assigned = out; }
    else                            { out_labels = out; }

    cudaFuncSetAttribute(assign_mma_kernel,
                         cudaFuncAttributeMaxDynamicSharedMemorySize, SM_BYTES);

    prep_kernel<<<B / 8, 256>>>(x, 1, B);
    prep_kernel<<<K / 8, 256>>>(cent, 0, K);
    csq_kernel<<<(K * 32) / 256, 256>>>(cent, K);
    assign_mma_kernel<<<B / TM, NTHREADS, SM_BYTES>>>(K);
    finalize_kernel<<<B, 128>>>(x, cent, out_labels, out_assigned, K);
}

// round 9
// speedup vs baseline: 1.0071x; 1.0071x over previous
#include <cuda_runtime.h>
#include <cuda_bf16.h>
#include <cstdint>

// ---------------------------------------------------------------------------
// KMeans assignment via warp-level bf16 HMMA (mma.sync, base sm_103 features).
//   x: (32768,512) f32, centroids: (2048,512) f32
//   labels = argmin_k ( c_sq[k] - 2*(x+eps).c_k ); assigned = centroids[labels]
// bf16x3 limbs: dot ~= xh.ch + xh.cl + xl.ch (fp32 acc), err ~1e-3 abs.
// Rows with (best2-best1) < MARGIN get an exact fp32 recompute in finalize.
// ---------------------------------------------------------------------------

#define EPSF   1e-6f
#define DIMS   512
#define MARGIN 0.02f
#define MAX_B  32768
#define MAX_K  2048

#define TM 128          // rows per CTA
#define TN 128          // centroids per n-tile
#define NTHREADS 256    // 8 warps: 4 (m) x 2 (n); warp tile 32x64

__device__ __nv_bfloat16 g_xpk[(size_t)MAX_B * 1024];   // [row][ hi512 | lo512 ]
__device__ __nv_bfloat16 g_cpk[(size_t)MAX_K * 1024];
__device__ float g_csq[MAX_K];
__device__ int   g_labels[MAX_B];
__device__ float g_gap[MAX_B];

// ------------------------------ helpers -------------------------------------
__device__ __forceinline__ uint32_t smem_u32(const void* p) {
    uint32_t a;
    asm("{ .reg .u64 t; cvta.to.shared.u64 t, %1; cvt.u32.u64 %0, t; }"
        : "=r"(a) : "l"(p));
    return a;
}
#define SWZ128(o) ((o) ^ (((o) >> 3) & 0x70))

__device__ __forceinline__ void cp_async16(uint32_t s, const void* g) {
    asm volatile("cp.async.cg.shared.global [%0], [%1], 16;"
                 :: "r"(s), "l"(g) : "memory");
}
#define CP_COMMIT() asm volatile("cp.async.commit_group;" ::: "memory")
#define CP_WAIT1()  asm volatile("cp.async.wait_group 1;" ::: "memory")

__device__ __forceinline__ void ldsm_x4(uint32_t a, uint32_t& r0, uint32_t& r1,
                                        uint32_t& r2, uint32_t& r3) {
    asm volatile("ldmatrix.sync.aligned.m8n8.x4.shared.b16 {%0,%1,%2,%3}, [%4];"
                 : "=r"(r0), "=r"(r1), "=r"(r2), "=r"(r3) : "r"(a));
}
__device__ __forceinline__ void ldsm_x2(uint32_t a, uint32_t& r0, uint32_t& r1) {
    asm volatile("ldmatrix.sync.aligned.m8n8.x2.shared.b16 {%0,%1}, [%2];"
                 : "=r"(r0), "=r"(r1) : "r"(a));
}
__device__ __forceinline__ void mma16816(float* d, const uint32_t* a,
                                         const uint32_t* b) {
    asm volatile(
        "mma.sync.aligned.m16n8k16.row.col.f32.bf16.bf16.f32 "
        "{%0,%1,%2,%3}, {%4,%5,%6,%7}, {%8,%9}, {%0,%1,%2,%3};"
        : "+f"(d[0]), "+f"(d[1]), "+f"(d[2]), "+f"(d[3])
        : "r"(a[0]), "r"(a[1]), "r"(a[2]), "r"(a[3]), "r"(b[0]), "r"(b[1]));
}
__device__ __forceinline__ uint32_t pack_bf(__nv_bfloat16 a, __nv_bfloat16 b) {
    __nv_bfloat162 t; t.x = a; t.y = b;
    return *reinterpret_cast<uint32_t*>(&t);
}
__device__ __forceinline__ unsigned sortable_f32(float f) {
    unsigned u = __float_as_uint(f);
    return (u & 0x80000000u) ? ~u : (u | 0x80000000u);
}
__device__ __forceinline__ float unsortable_f32(unsigned u) {
    return (u & 0x80000000u) ? __uint_as_float(u ^ 0x80000000u)
                             : __uint_as_float(~u);
}

// ---- prep: split fp32 rows into bf16 hi/lo limbs: [hi 512 | lo 512] --------
// warp per row: lane-coalesced loads and stores.
__global__ void prep_kernel(const float* __restrict__ src, int is_x, int nrows) {
    int warp = (blockIdx.x * 256 + threadIdx.x) >> 5;
    int lane = threadIdx.x & 31;
    if (warp >= nrows) return;
    const int row = warp;
    const float eps = is_x ? EPSF : 0.f;
    const float4* s4 = reinterpret_cast<const float4*>(src + (size_t)row * DIMS);
    uint2* dst = reinterpret_cast<uint2*>(is_x ? g_xpk : g_cpk);  // row stride 256
#pragma unroll
    for (int q = 0; q < 4; ++q) {
        float4 f = s4[q * 32 + lane];
        float e0 = f.x + eps, e1 = f.y + eps, e2 = f.z + eps, e3 = f.w + eps;
        __nv_bfloat16 h0 = __float2bfloat16(e0), h1 = __float2bfloat16(e1);
        __nv_bfloat16 h2 = __float2bfloat16(e2), h3 = __float2bfloat16(e3);
        __nv_bfloat16 l0 = __float2bfloat16(e0 - __bfloat162float(h0));
        __nv_bfloat16 l1 = __float2bfloat16(e1 - __bfloat162float(h1));
        __nv_bfloat16 l2 = __float2bfloat16(e2 - __bfloat162float(h2));
        __nv_bfloat16 l3 = __float2bfloat16(e3 - __bfloat162float(h3));
        dst[(size_t)row * 256 + q * 32 + lane] =
            make_uint2(pack_bf(h0, h1), pack_bf(h2, h3));
        dst[(size_t)row * 256 + 128 + q * 32 + lane] =
            make_uint2(pack_bf(l0, l1), pack_bf(l2, l3));
    }
}

// ---- centroid squared norms (warp per row) ----------------------------------
__global__ void csq_kernel(const float* __restrict__ cent, int K) {
    int gt = blockIdx.x * 256 + threadIdx.x;
    int w = gt >> 5, lane = gt & 31;
    if (w >= K) return;
    const float4* row = reinterpret_cast<const float4*>(cent + (size_t)w * DIMS);
    float s = 0.f;
#pragma unroll
    for (int i = 0; i < 4; ++i) {
        float4 v = row[lane + 32 * i];
        s += v.x * v.x + v.y * v.y + v.z * v.z + v.w * v.w;
    }
#pragma unroll
    for (int o = 16; o; o >>= 1) s += __shfl_xor_sync(0xffffffffu, s, o);
    if (!lane) g_csq[w] = s;
}

// ---- main HMMA kernel --------------------------------------------------------
// smem: best1[128] u64, best2[128] u32, then 3 stages of (A 16KB + B 16KB).
#define STAGE_BYTES (TM * 128 + TN * 128)  // 32768
#define SM_STAGE0   2048
#define SM_BYTES    (SM_STAGE0 + 3 * STAGE_BYTES)  // 100352

__global__ __launch_bounds__(NTHREADS, 2)
void assign_mma_kernel(int K) {
    extern __shared__ char smem[];
    unsigned long long* best1 = reinterpret_cast<unsigned long long*>(smem);
    unsigned* best2 = reinterpret_cast<unsigned*>(smem + TM * 8);
    const uint32_t sb = smem_u32(smem);

    const int tid = threadIdx.x;
    const int lane = tid & 31;
    const int wid = tid >> 5;
    const int warp_m = wid & 3;   // 4 warps along M (32 rows each)
    const int warp_n = wid >> 2;  // 2 warps along N (64 cols each)
    const int m0 = blockIdx.x * TM;

    if (tid < TM) { best1[tid] = ~0ull; best2[tid] = 0xFFFFFFFFu; }

    const int NT = K / TN;          // 16 n-tiles
    const int T = NT * 24;          // 24 k-iters per n-tile (3 products x 8)

    auto load_stage = [&](int j) {
        const int nt = j / 24, kc = j % 24;
        const int p = kc >> 3, c = kc & 7;
        const int ka = (p < 2 ? 0 : 512) + c * 64;
        const int kb = (p == 1 ? 512 : 0) + c * 64;
        const int n0 = nt * TN;
        const uint32_t abase = sb + SM_STAGE0 + (j % 3) * STAGE_BYTES;
        const uint32_t bbase = abase + TM * 128;
#pragma unroll
        for (int i = 0; i < 4; ++i) {  // A: 1024 16B chunks / 256 thr
            int idx = i * NTHREADS + tid;
            int r = idx >> 3, q = idx & 7;
            cp_async16(abase + SWZ128(r * 128 + q * 16),
                       g_xpk + (size_t)(m0 + r) * 1024 + ka + q * 8);
        }
#pragma unroll
        for (int i = 0; i < 4; ++i) {  // B: 1024 chunks / 256 thr
            int idx = i * NTHREADS + tid;
            int r = idx >> 3, q = idx & 7;
            cp_async16(bbase + SWZ128(r * 128 + q * 16),
                       g_cpk + (size_t)(n0 + r) * 1024 + kb + q * 8);
        }
    };

    float acc[2][8][4];
#pragma unroll
    for (int fm = 0; fm < 2; ++fm)
#pragma unroll
        for (int fn = 0; fn < 8; ++fn)
#pragma unroll
            for (int q = 0; q < 4; ++q) acc[fm][fn][q] = 0.f;

    float rb1[4], rb2[4];
    int ri[4];
#pragma unroll
    for (int s = 0; s < 4; ++s) {
        rb1[s] = __int_as_float(0x7f800000);
        rb2[s] = rb1[s];
        ri[s] = 0;
    }

    load_stage(0); CP_COMMIT();
    load_stage(1); CP_COMMIT();

    for (int j = 0; j < T; ++j) {
        CP_WAIT1();
        __syncthreads();
        const uint32_t abase = sb + SM_STAGE0 + (j % 3) * STAGE_BYTES;
        const uint32_t bbase = abase + TM * 128;

#pragma unroll
        for (int ks = 0; ks < 4; ++ks) {
            uint32_t a[2][4], b[8][2];
#pragma unroll
            for (int fm = 0; fm < 2; ++fm) {
                int r = warp_m * 32 + fm * 16 + (lane & 15);
                uint32_t addr = abase +
                    SWZ128((uint32_t)(r * 128 + ks * 32 + ((lane >> 4) & 1) * 16));
                ldsm_x4(addr, a[fm][0], a[fm][1], a[fm][2], a[fm][3]);
            }
#pragma unroll
            for (int fn = 0; fn < 8; ++fn) {
                int r = warp_n * 64 + fn * 8 + (lane & 7);
                uint32_t addr = bbase +
                    SWZ128((uint32_t)(r * 128 + ks * 32 + ((lane >> 3) & 1) * 16));
                ldsm_x2(addr, b[fn][0], b[fn][1]);
            }
#pragma unroll
            for (int fm = 0; fm < 2; ++fm)
#pragma unroll
                for (int fn = 0; fn < 8; ++fn)
                    mma16816(acc[fm][fn], a[fm], b[fn]);
        }

        if (j + 2 < T) load_stage(j + 2);
        CP_COMMIT();

        if ((j % 24) == 23) {
            const int n0 = (j / 24) * TN;
#pragma unroll
            for (int fn = 0; fn < 8; ++fn) {
                int c0 = n0 + warp_n * 64 + fn * 8 + (lane & 3) * 2;
                float q0 = g_csq[c0], q1 = g_csq[c0 + 1];
#pragma unroll
                for (int fm = 0; fm < 2; ++fm) {
                    float s00 = fmaf(-2.f, acc[fm][fn][0], q0);
                    float s01 = fmaf(-2.f, acc[fm][fn][1], q1);
                    float s10 = fmaf(-2.f, acc[fm][fn][2], q0);
                    float s11 = fmaf(-2.f, acc[fm][fn][3], q1);
                    int s0 = fm * 2, s1 = fm * 2 + 1;
                    if (s00 < rb1[s0]) { rb2[s0] = rb1[s0]; rb1[s0] = s00; ri[s0] = c0; }
                    else if (s00 < rb2[s0]) rb2[s0] = s00;
                    if (s01 < rb1[s0]) { rb2[s0] = rb1[s0]; rb1[s0] = s01; ri[s0] = c0 + 1; }
                    else if (s01 < rb2[s0]) rb2[s0] = s01;
                    if (s10 < rb1[s1]) { rb2[s1] = rb1[s1]; rb1[s1] = s10; ri[s1] = c0; }
                    else if (s10 < rb2[s1]) rb2[s1] = s10;
                    if (s11 < rb1[s1]) { rb2[s1] = rb1[s1]; rb1[s1] = s11; ri[s1] = c0 + 1; }
                    else if (s11 < rb2[s1]) rb2[s1] = s11;
                    acc[fm][fn][0] = 0.f; acc[fm][fn][1] = 0.f;
                    acc[fm][fn][2] = 0.f; acc[fm][fn][3] = 0.f;
                }
            }
        }
    }

    // ---- final reduction: lanes sharing a row (same lane>>2) merge ----------
#pragma unroll
    for (int s = 0; s < 4; ++s) {
#pragma unroll
        for (int d = 1; d <= 2; d <<= 1) {
            float ob1 = __shfl_xor_sync(0xffffffffu, rb1[s], d);
            float ob2 = __shfl_xor_sync(0xffffffffu, rb2[s], d);
            int oi = __shfl_xor_sync(0xffffffffu, ri[s], d);
            if (ob1 < rb1[s] || (ob1 == rb1[s] && oi < ri[s])) {
                rb2[s] = fminf(rb1[s], ob2);
                rb1[s] = ob1; ri[s] = oi;
            } else {
                rb2[s] = fminf(rb2[s], ob1);
            }
        }
    }
    if ((lane & 3) == 0) {
#pragma unroll
        for (int s = 0; s < 4; ++s) {
            int row = warp_m * 32 + (s >> 1) * 16 + (lane >> 2) + (s & 1) * 8;
            unsigned long long key =
                ((unsigned long long)sortable_f32(rb1[s]) << 32) | (unsigned)ri[s];
            atomicMin(&best1[row], key);
        }
    }
    __syncthreads();
    if ((lane & 3) == 0) {
#pragma unroll
        for (int s = 0; s < 4; ++s) {
            int row = warp_m * 32 + (s >> 1) * 16 + (lane >> 2) + (s & 1) * 8;
            unsigned long long k1 = best1[row];
            float contrib = ((int)(k1 & 0xFFFFFFFFull) == ri[s]) ? rb2[s] : rb1[s];
            atomicMin(&best2[row], sortable_f32(contrib));
        }
    }
    __syncthreads();
    if (tid < TM) {
        unsigned long long k1 = best1[tid];
        g_labels[m0 + tid] = (int)(k1 & 0xFFFFFFFFull);
        g_gap[m0 + tid] =
            unsortable_f32(best2[tid]) - unsortable_f32((unsigned)(k1 >> 32));
    }
}

// ---- finalize: exact recompute for ambiguous rows + labels + gather ---------
__global__ __launch_bounds__(128)
void finalize_kernel(const float* __restrict__ x, const float* __restrict__ cent,
                     float* __restrict__ out_labels,
                     float* __restrict__ out_assigned, int K) {
    const int row = blockIdx.x;
    const int tid = threadIdx.x;
    __shared__ float xr[DIMS];
    __shared__ unsigned long long best;
    __shared__ int s_label;

    if (g_gap[row] < MARGIN) {
        if (tid == 0) best = ~0ull;
        reinterpret_cast<float4*>(xr)[tid] =
            reinterpret_cast<const float4*>(x + (size_t)row * DIMS)[tid];
        __syncthreads();
        if (tid < DIMS) {  // add eps (128 thr x 4)
            float4* p = reinterpret_cast<float4*>(xr) + tid;
            float4 v = *p;
            v.x += EPSF; v.y += EPSF; v.z += EPSF; v.w += EPSF;
            *p = v;
        }
        __syncthreads();
        const float4* xr4 = reinterpret_cast<const float4*>(xr);
        unsigned long long lbest = ~0ull;
        for (int c = tid; c < K; c += 128) {
            const float4* cr = reinterpret_cast<const float4*>(cent + (size_t)c * DIMS);
            float s = 0.f;
#pragma unroll 8
            for (int i = 0; i < DIMS / 4; ++i) {
                float4 v = cr[i], u = xr4[i];
                s += u.x * v.x + u.y * v.y + u.z * v.z + u.w * v.w;
            }
            float score = g_csq[c] - 2.f * s;
            unsigned long long key =
                ((unsigned long long)sortable_f32(score) << 32) | (unsigned)c;
            if (key < lbest) lbest = key;
        }
        atomicMin(&best, lbest);
        __syncthreads();
        if (tid == 0) s_label = (int)(best & 0xFFFFFFFFull);
    } else {
        if (tid == 0) s_label = g_labels[row];
    }
    __syncthreads();
    const int lab = s_label;
    if (out_labels && tid == 0) out_labels[row] = (float)lab;
    if (out_assigned) {
        reinterpret_cast<float4*>(out_assigned + (size_t)row * DIMS)[tid] =
            reinterpret_cast<const float4*>(cent + (size_t)lab * DIMS)[tid];
    }
}

// ---------------------------------------------------------------------------
extern "C" void kernel_launch(void* const* d_in, const int* in_sizes, int n_in,
                              void* d_out, int out_size) {
    const float* x = (const float*)d_in[0];
    const float* cent = (const float*)d_in[1];
    const int B = in_sizes[0] / DIMS;  // 32768
    const int K = in_sizes[1] / DIMS;  // 2048

    float* out = (float*)d_out;
    float* out_labels = nullptr;
    float* out_assigned = nullptr;
    if (out_size == B * (DIMS + 1)) { out_labels = out; out_assigned = out + B; }
    else if (out_size == B * DIMS)  { out_assigned = out; }
    else                            { out_labels = out; }

    cudaFuncSetAttribute(assign_mma_kernel,
                         cudaFuncAttributeMaxDynamicSharedMemorySize, SM_BYTES);

    prep_kernel<<<B / 8, 256>>>(x, 1, B);
    prep_kernel<<<K / 8, 256>>>(cent, 0, K);
    csq_kernel<<<(K * 32) / 256, 256>>>(cent, K);
    assign_mma_kernel<<<B / TM, NTHREADS, SM_BYTES>>>(K);
    finalize_kernel<<<B, 128>>>(x, cent, out_labels, out_assigned, K);
}